// round 8
// baseline (speedup 1.0000x reference)
#include <cuda_runtime.h>
#include <cuda_bf16.h>

// Problem constants (fixed by the reference: pc (4,4096,3), mask (4,4096,30))
#define BQ_B 4
#define BQ_N 4096
#define BQ_C 30
#define BQ_K 16
#define BQ_R2 0.04f

#define WARPS_PER_BLOCK 8
#define NUM_QUERIES (BQ_B * BQ_N)                       // 16384
#define PERSIST_BLOCKS (148 * 4)                        // 592 persistent blocks

__device__ float    g_qloss[NUM_QUERIES];   // per-query loss (assignment-independent)
__device__ unsigned g_qhead = 0;            // dynamic query queue head
__device__ unsigned g_ticket = 0;           // finished-block ticket

__global__ __launch_bounds__(WARPS_PER_BLOCK * 32)
void ballq_loss_kernel(const float* __restrict__ pc,
                       const float* __restrict__ mask,
                       float* __restrict__ out) {
    const int warp = threadIdx.x >> 5;
    const int lane = threadIdx.x & 31;

    __shared__ int sidx[WARPS_PER_BLOCK][BQ_K];

    // ---- Persistent loop: warps grab queries dynamically ----
    for (;;) {
        unsigned q;
        if (lane == 0) q = atomicAdd(&g_qhead, 1u);
        q = __shfl_sync(0xffffffffu, q, 0);
        if (q >= NUM_QUERIES) break;

        const int b = q >> 12;                           // q / 4096
        const int n = q & (BQ_N - 1);                    // q % 4096

        const float* __restrict__ pcb = pc + (size_t)b * BQ_N * 3;

        // Query point (broadcast load, same address across warp)
        const float qx = pcb[n * 3 + 0];
        const float qy = pcb[n * 3 + 1];
        const float qz = pcb[n * 3 + 2];
        const float qsq = qx * qx + qy * qy + qz * qz;

        // ---- Ball-query scan: first K indices (index order) with d2 < R2 ----
        // R4's proven loop: 128 candidates/iter, 12 scalar loads up front,
        // guarded 32-bit ballots with serial lane-0 peel.
        // d2 = qsq + msq - 2*dot matches the reference's algebraic form so
        // boundary rounding errors correlate with the reference.
        int cnt = 0;  // uniform across the warp
        for (int base = 0; base < BQ_N && cnt < BQ_K; base += 128) {
            float d2[4];
#pragma unroll
            for (int j = 0; j < 4; j++) {
                const int m = base + j * 32 + lane;      // N % 128 == 0
                const float mx = pcb[m * 3 + 0];
                const float my = pcb[m * 3 + 1];
                const float mz = pcb[m * 3 + 2];
                const float msq = mx * mx + my * my + mz * mz;
                const float dot = qx * mx + qy * my + qz * mz;
                d2[j] = qsq + msq - 2.0f * dot;
            }
#pragma unroll
            for (int j = 0; j < 4; j++) {
                if (cnt < BQ_K) {                        // uniform predicate
                    unsigned bal = __ballot_sync(0xffffffffu, d2[j] < BQ_R2);
                    while (bal && cnt < BQ_K) {          // lowest index first
                        const int l = __ffs(bal) - 1;
                        if (lane == 0) sidx[warp][cnt] = base + j * 32 + l;
                        cnt++;
                        bal &= bal - 1;
                    }
                }
            }
        }
        // Pad remaining slots with first found index (cnt >= 1: self hit)
        if (lane == 0) {
            const int f = sidx[warp][0];
            for (int j = cnt; j < BQ_K; j++) sidx[warp][j] = f;
        }
        __syncwarp();

        // ---- Loss: lane c handles channel c (c < 30) ----
        float acc = 0.0f;
        if (lane < BQ_C) {
            const float* __restrict__ mb = mask + (size_t)b * BQ_N * BQ_C;
            const float mq = mb[n * BQ_C + lane];
#pragma unroll
            for (int j = 0; j < BQ_K; j++) {
                const int id = sidx[warp][j];
                acc += fabsf(mq - mb[id * BQ_C + lane]);
            }
        }
        // Warp reduce (lanes 30,31 contribute 0)
#pragma unroll
        for (int off = 16; off; off >>= 1)
            acc += __shfl_down_sync(0xffffffffu, acc, off);

        if (lane == 0) g_qloss[q] = acc;   // per-query: assignment-independent
    }

    // ---- Block-finished ticket ----
    __syncthreads();
    __shared__ bool is_last;
    if (threadIdx.x == 0) {
        __threadfence();                                  // publish g_qloss writes
        unsigned t = atomicAdd(&g_ticket, 1u);
        is_last = (t == PERSIST_BLOCKS - 1);
    }
    __syncthreads();

    // ---- Fused final reduction: last block, fixed order, deterministic ----
    if (is_last) {
        __shared__ float sh[256];
        float s = 0.0f;
        for (int i = threadIdx.x; i < NUM_QUERIES; i += 256)
            s += g_qloss[i];                              // fixed per-thread order
        sh[threadIdx.x] = s;
        __syncthreads();
#pragma unroll
        for (int off = 128; off; off >>= 1) {
            if (threadIdx.x < off) sh[threadIdx.x] += sh[threadIdx.x + off];
            __syncthreads();
        }
        if (threadIdx.x == 0) {
            out[0] = sh[0] * (1.0f / ((float)BQ_K * (float)NUM_QUERIES));
            g_ticket = 0;                                 // reset for next replay
            g_qhead = 0;
        }
    }
}

extern "C" void kernel_launch(void* const* d_in, const int* in_sizes, int n_in,
                              void* d_out, int out_size) {
    const float* pc   = (const float*)d_in[0];   // (4, 4096, 3) float32
    const float* mask = (const float*)d_in[1];   // (4, 4096, 30) float32
    float* out = (float*)d_out;                  // scalar float32

    ballq_loss_kernel<<<PERSIST_BLOCKS, WARPS_PER_BLOCK * 32>>>(pc, mask, out);
}

// round 10
// speedup vs baseline: 1.8498x; 1.8498x over previous
#include <cuda_runtime.h>
#include <cuda_bf16.h>

// Problem constants (fixed by the reference: pc (4,4096,3), mask (4,4096,30))
#define BQ_B 4
#define BQ_N 4096
#define BQ_C 30
#define BQ_K 16
#define BQ_R2 0.04f

#define WARPS_PER_BLOCK 8
#define NUM_QUERIES (BQ_B * BQ_N)                       // 16384
#define NUM_BLOCKS (NUM_QUERIES / WARPS_PER_BLOCK)      // 2048

__device__ float    g_partials[NUM_BLOCKS];
__device__ unsigned g_ticket = 0;   // reset by the last block each launch

__global__ __launch_bounds__(WARPS_PER_BLOCK * 32)
void ballq_loss_kernel(const float* __restrict__ pc,
                       const float* __restrict__ mask,
                       float* __restrict__ out) {
    const int warp = threadIdx.x >> 5;
    const int lane = threadIdx.x & 31;
    const int q = blockIdx.x * WARPS_PER_BLOCK + warp;   // query id, 0..16383
    const int b = q >> 12;                               // q / 4096
    const int n = q & (BQ_N - 1);                        // q % 4096

    const float* __restrict__ pcb = pc + (size_t)b * BQ_N * 3;

    // Query point (broadcast load, same address across warp)
    const float qx = pcb[n * 3 + 0];
    const float qy = pcb[n * 3 + 1];
    const float qz = pcb[n * 3 + 2];
    const float qsq = qx * qx + qy * qy + qz * qz;

    __shared__ int sidx[WARPS_PER_BLOCK][BQ_K];

    // ---- Ball-query scan: first K indices (index order) with d2 < R2 ----
    // Lane L owns candidates base+4L .. base+4L+3: their 12 xyz floats are
    // 48 contiguous 16B-aligned bytes -> 3 LDG.128 per lane per 128 cands.
    // One ballot per 128 candidates ("lane has any hit") + per-lane nibble;
    // peel ascending hit-lanes (== ascending index, lane-major layout).
    // d2 = qsq + msq - 2*dot matches the reference's algebraic form so
    // boundary rounding errors correlate with the reference.
    const float4* __restrict__ pl =
        (const float4*)(pcb + (size_t)lane * 12);        // 48B per lane

    int cnt = 0;  // uniform across the warp
    for (int base = 0; base < BQ_N && cnt < BQ_K; base += 128, pl += 96) {
        // 3 wide loads cover this lane's 4 candidates (N % 128 == 0)
        const float4 fa = pl[0];
        const float4 fb = pl[1];
        const float4 fc = pl[2];

        // Unpack candidate xyz (c0..c3 ascending index within lane)
        const float x0 = fa.x, y0 = fa.y, z0 = fa.z;
        const float x1 = fa.w, y1 = fb.x, z1 = fb.y;
        const float x2 = fb.z, y2 = fb.w, z2 = fc.x;
        const float x3 = fc.y, y3 = fc.z, z3 = fc.w;

        unsigned nib = 0u;
        {
            const float msq = x0 * x0 + y0 * y0 + z0 * z0;
            const float dot = qx * x0 + qy * y0 + qz * z0;
            if (qsq + msq - 2.0f * dot < BQ_R2) nib |= 1u;
        }
        {
            const float msq = x1 * x1 + y1 * y1 + z1 * z1;
            const float dot = qx * x1 + qy * y1 + qz * z1;
            if (qsq + msq - 2.0f * dot < BQ_R2) nib |= 2u;
        }
        {
            const float msq = x2 * x2 + y2 * y2 + z2 * z2;
            const float dot = qx * x2 + qy * y2 + qz * z2;
            if (qsq + msq - 2.0f * dot < BQ_R2) nib |= 4u;
        }
        {
            const float msq = x3 * x3 + y3 * y3 + z3 * z3;
            const float dot = qx * x3 + qy * y3 + qz * z3;
            if (qsq + msq - 2.0f * dot < BQ_R2) nib |= 8u;
        }

        unsigned balAny = __ballot_sync(0xffffffffu, nib != 0u);
        // Peel hit-lanes lowest-first (ascending candidate index)
        while (balAny && cnt < BQ_K) {
            const int L = __ffs(balAny) - 1;
            unsigned nb = __shfl_sync(0xffffffffu, nib, L);  // uniform loop
            const int bi = base + L * 4;
            while (nb && cnt < BQ_K) {
                const int jj = __ffs(nb) - 1;
                if (lane == 0) sidx[warp][cnt] = bi + jj;
                cnt++;
                nb &= nb - 1u;
            }
            balAny &= balAny - 1u;
        }
    }
    // Pad remaining slots with the first found index (cnt >= 1: self hit)
    if (lane == 0) {
        const int f = sidx[warp][0];
        for (int j = cnt; j < BQ_K; j++) sidx[warp][j] = f;
    }
    __syncwarp();

    // ---- Loss: lane c handles channel c (c < 30); neighbor rows coalesced ----
    float acc = 0.0f;
    if (lane < BQ_C) {
        const float* __restrict__ mb = mask + (size_t)b * BQ_N * BQ_C;
        const float mq = mb[n * BQ_C + lane];
#pragma unroll
        for (int j = 0; j < BQ_K; j++) {
            const int id = sidx[warp][j];
            acc += fabsf(mq - mb[id * BQ_C + lane]);
        }
    }
    // Warp reduce (lanes 30,31 contribute 0)
#pragma unroll
    for (int off = 16; off; off >>= 1)
        acc += __shfl_down_sync(0xffffffffu, acc, off);

    __shared__ float wl[WARPS_PER_BLOCK];
    if (lane == 0) wl[warp] = acc;
    __syncthreads();

    // Per-block partial in fixed order (no float atomics -> deterministic)
    __shared__ bool is_last;
    if (threadIdx.x == 0) {
        float s = 0.0f;
#pragma unroll
        for (int w2 = 0; w2 < WARPS_PER_BLOCK; w2++) s += wl[w2];
        g_partials[blockIdx.x] = s;
        __threadfence();                                  // publish partial
        unsigned t = atomicAdd(&g_ticket, 1u);            // int ticket only
        is_last = (t == NUM_BLOCKS - 1);
    }
    __syncthreads();

    // ---- Fused final reduction: last block, fixed order, deterministic ----
    if (is_last) {
        __shared__ float sh[256];
        float s = 0.0f;
        for (int i = threadIdx.x; i < NUM_BLOCKS; i += 256)
            s += g_partials[i];
        sh[threadIdx.x] = s;
        __syncthreads();
#pragma unroll
        for (int off = 128; off; off >>= 1) {
            if (threadIdx.x < off) sh[threadIdx.x] += sh[threadIdx.x + off];
            __syncthreads();
        }
        if (threadIdx.x == 0) {
            out[0] = sh[0] * (1.0f / ((float)BQ_K * (float)NUM_QUERIES));
            g_ticket = 0;                                 // reset for next replay
        }
    }
}

extern "C" void kernel_launch(void* const* d_in, const int* in_sizes, int n_in,
                              void* d_out, int out_size) {
    const float* pc   = (const float*)d_in[0];   // (4, 4096, 3) float32
    const float* mask = (const float*)d_in[1];   // (4, 4096, 30) float32
    float* out = (float*)d_out;                  // scalar float32

    ballq_loss_kernel<<<NUM_BLOCKS, WARPS_PER_BLOCK * 32>>>(pc, mask, out);
}